// round 13
// baseline (speedup 1.0000x reference)
#include <cuda_runtime.h>

// ---------------------------------------------------------------------------
// MWDLSTMGCT: only the low-pass wavelet chain + LSTM-3 affect the output.
//   xl1 = avgpool2(sigmoid(x @ W1L^T + b1L))        (256 x 512)
//   xl2 = avgpool2(sigmoid(xl1 @ W2L^T + b2L))      (256 x 256)
//   h   = LSTM(xl2 as scalar sequence; Wih3,Whh3,b3), final hidden (256 x 100)
//   out = h @ Wout^T + bout                          (256 x 1)
// ---------------------------------------------------------------------------

#define NBATCH 256
#define HID    100
#define GATES  400   // 4*HID
#define TSTEPS 256

__device__ __align__(16) float g_xl1[256 * 512];
__device__ __align__(16) float g_xl2[256 * 256];

__device__ __forceinline__ float sigf(float x) { return 1.f / (1.f + __expf(-x)); }
// tanh(x) = 1 - 2/(exp(2x)+1); exact saturation.
__device__ __forceinline__ float tanh_fast(float x) {
    return 1.f - 2.f / (__expf(2.f * x) + 1.f);
}

// ---------------------------------------------------------------------------
// Fused GEMM (C = A @ W^T), bias, sigmoid, avgpool2 along N.  (unchanged R10)
// Tile 32(M) x 64(N), K-slices of 16, triple-buffered smem, depth-3 LDG
// pipeline, 256 threads, microtile 4x2. Grid (N/64, M/32).
// ---------------------------------------------------------------------------
template <int K>
__device__ __forceinline__ void gemm_sig_pool_body(
    const float* __restrict__ A, const float* __restrict__ W,
    const float* __restrict__ bias, float* __restrict__ out, int halfN)
{
    __shared__ __align__(16) float As[3][16][32];
    __shared__ __align__(16) float Bs[3][16][64];

    const int m0 = blockIdx.y * 32;
    const int n0 = blockIdx.x * 64;
    const int tid = threadIdx.x;

    const int lmB = tid >> 2;
    const int lkB = (tid & 3) * 4;
    const float* Bg = W + (n0 + lmB) * K + lkB;
    const bool hasA = tid < 128;
    const int lmA = (tid & 127) >> 2;
    const int lkA = (tid & 3) * 4;
    const float* Ag = A + (m0 + lmA) * K + lkA;

    const int tx = tid & 31;
    const int ty = tid >> 5;

    float acc[4][2] = {};
    const int NT = K / 16;

    auto ldA = [&](int s) -> float4 {
        return hasA ? *(const float4*)(Ag + s * 16) : make_float4(0.f, 0.f, 0.f, 0.f);
    };
    auto ldB = [&](int s) -> float4 { return *(const float4*)(Bg + s * 16); };
    auto stsA = [&](int buf, float4 v) {
        if (hasA) {
            As[buf][lkA + 0][lmA] = v.x; As[buf][lkA + 1][lmA] = v.y;
            As[buf][lkA + 2][lmA] = v.z; As[buf][lkA + 3][lmA] = v.w;
        }
    };
    auto stsB = [&](int buf, float4 v) {
        Bs[buf][lkB + 0][lmB] = v.x; Bs[buf][lkB + 1][lmB] = v.y;
        Bs[buf][lkB + 2][lmB] = v.z; Bs[buf][lkB + 3][lmB] = v.w;
    };
    auto compute = [&](int buf) {
        #pragma unroll
        for (int kk = 0; kk < 16; kk++) {
            float4 av = *(const float4*)&As[buf][kk][ty * 4];
            float2 bv = *(const float2*)&Bs[buf][kk][tx * 2];
            acc[0][0] = fmaf(av.x, bv.x, acc[0][0]);
            acc[0][1] = fmaf(av.x, bv.y, acc[0][1]);
            acc[1][0] = fmaf(av.y, bv.x, acc[1][0]);
            acc[1][1] = fmaf(av.y, bv.y, acc[1][1]);
            acc[2][0] = fmaf(av.z, bv.x, acc[2][0]);
            acc[2][1] = fmaf(av.z, bv.y, acc[2][1]);
            acc[3][0] = fmaf(av.w, bv.x, acc[3][0]);
            acc[3][1] = fmaf(av.w, bv.y, acc[3][1]);
        }
    };

    float4 a0 = ldA(0), b0 = ldB(0);
    float4 a1 = ldA(1), b1 = ldB(1);
    float4 a2 = ldA(2), b2 = ldB(2);
    stsA(0, a0); stsB(0, b0);
    __syncthreads();

    for (int i = 0; i < NT; i += 3) {
        {
            compute(0);
            if (i + 3 < NT) { a0 = ldA(i + 3); b0 = ldB(i + 3); }
            if (i + 1 < NT) { stsA(1, a1); stsB(1, b1); }
            __syncthreads();
        }
        if (i + 1 < NT) {
            compute(1);
            if (i + 4 < NT) { a1 = ldA(i + 4); b1 = ldB(i + 4); }
            if (i + 2 < NT) { stsA(2, a2); stsB(2, b2); }
            __syncthreads();
        }
        if (i + 2 < NT) {
            compute(2);
            if (i + 5 < NT) { a2 = ldA(i + 5); b2 = ldB(i + 5); }
            if (i + 3 < NT) { stsA(0, a0); stsB(0, b0); }
            __syncthreads();
        }
    }

    const float bn0 = bias[n0 + tx * 2 + 0];
    const float bn1 = bias[n0 + tx * 2 + 1];
    const int ocol = (n0 >> 1) + tx;
    #pragma unroll
    for (int i = 0; i < 4; i++) {
        const int m = m0 + ty * 4 + i;
        float s0 = sigf(acc[i][0] + bn0);
        float s1 = sigf(acc[i][1] + bn1);
        out[m * halfN + ocol] = 0.5f * (s0 + s1);
    }
}

__global__ void __launch_bounds__(256) gemm1_kernel(
    const float* __restrict__ A, const float* __restrict__ W,
    const float* __restrict__ bias)
{
    gemm_sig_pool_body<1024>(A, W, bias, g_xl1, 512);
}

__global__ void __launch_bounds__(256) gemm2_kernel(
    const float* __restrict__ W, const float* __restrict__ bias)
{
    gemm_sig_pool_body<512>(g_xl1, W, bias, g_xl2, 256);
}

// ---------------------------------------------------------------------------
// LSTM-3: persistent per-CTA, 2 rows per CTA, SPLIT-K gates + ROW-STAGGERED
// software pipeline. 896 threads (28 warps, 72-reg cap):
//   t in [0,400)   : half-A of gate t (k in [0,50), + wih*x + b term)
//   t in [400,800) : half-B of gate t-400 (k in [50,100), wih=b=0, identical
//                    instruction stream -> no divergence)
//   t in [800,896) : 96 epilogue threads (warps 25..27, disjoint from gate
//                    warps). While gates compute z(row, s), the epilogue
//                    applies the nonlinearity to the PREVIOUS phase's
//                    z(row^1), hiding the MUFU chain under the gate GEMV.
// One barrier per phase, 2 phases per step; p-loop unrolled x2 so `row` is
// compile-time (no dynamic register indexing anywhere).
// ---------------------------------------------------------------------------
__global__ void __launch_bounds__(896, 1) lstm_kernel(
    const float* __restrict__ Wih, const float* __restrict__ Whh,
    const float* __restrict__ b3,  const float* __restrict__ Wout,
    const float* __restrict__ bout, float* __restrict__ out)
{
    const int r0 = blockIdx.x * 2;
    const int t = threadIdx.x;

    __shared__ __align__(16) float h0_s[HID];
    __shared__ __align__(16) float h1_s[HID];
    __shared__ float zA[2][GATES];
    __shared__ float zB[2][GATES];
    __shared__ float x_s[2][TSTEPS];
    __shared__ float red0[HID], red1[HID];

    const bool isGate = t < 800;
    const bool halfA = t < 400;
    const int g = halfA ? t : t - 400;
    const int kb = halfA ? 0 : 50;

    float wreg[50];
    float wih_g = 0.f, bg = 0.f;
    float* zr0 = &zA[0][0];
    float* zr1 = &zA[1][0];
    if (isGate) {
        const float* wrow = Whh + g * HID + kb;
        #pragma unroll
        for (int k = 0; k < 50; k += 2) {
            float2 w = *(const float2*)(wrow + k);
            wreg[k] = w.x; wreg[k + 1] = w.y;
        }
        if (halfA) { wih_g = Wih[g]; bg = b3[g]; }
        zr0 = halfA ? &zA[0][g] : &zB[0][g];
        zr1 = halfA ? &zA[1][g] : &zB[1][g];
    }
    if (t < TSTEPS) {
        x_s[0][t] = g_xl2[r0 * TSTEPS + t];
        x_s[1][t] = g_xl2[(r0 + 1) * TSTEPS + t];
    }
    if (t < HID) { h0_s[t] = 0.f; h1_s[t] = 0.f; }

    // Epilogue thread state: j owns hidden unit j (both rows); j<4 also 96+j.
    const bool isEpi = t >= 800;
    const int j = t - 800;                       // 0..95
    const bool hasB = isEpi && (j < HID - 96);
    float cA0 = 0.f, cA1 = 0.f, cB0 = 0.f, cB1 = 0.f;
    __syncthreads();

    // Gate GEMV for one row (compile-time row via unrolled bodies).
    auto gate_phase = [&](const float* __restrict__ hs, float xv, float* zdst) {
        float za = fmaf(wih_g, xv, bg);
        float zb = 0.f;
        const float2* h2 = (const float2*)(hs + kb);
        #pragma unroll
        for (int k = 0; k < 25; k++) {
            float2 h = h2[k];
            za = fmaf(wreg[2 * k],     h.x, za);
            zb = fmaf(wreg[2 * k + 1], h.y, zb);
        }
        *zdst = za + zb;
    };
    // Epilogue for one (row, unit): z = zA+zB, gate math, write h.
    auto epi_unit = [&](int row, int u, float& c, float* __restrict__ hs) {
        float iz = zA[row][u]           + zB[row][u];
        float fz = zA[row][HID + u]     + zB[row][HID + u];
        float gz = zA[row][2 * HID + u] + zB[row][2 * HID + u];
        float oz = zA[row][3 * HID + u] + zB[row][3 * HID + u];
        c = sigf(fz) * c + sigf(iz) * tanh_fast(gz);
        hs[u] = sigf(oz) * tanh_fast(c);
    };

    for (int s = 0; s < TSTEPS; s++) {
        // Phase 2s: gates -> z(row0, s); epi -> h(row1, s-1).
        if (isGate) {
            gate_phase(h0_s, x_s[0][s], zr0);
        } else if (s > 0) {
            epi_unit(1, j, cA1, h1_s);
            if (hasB) epi_unit(1, 96 + j, cB1, h1_s);
        }
        __syncthreads();
        // Phase 2s+1: gates -> z(row1, s); epi -> h(row0, s).
        if (isGate) {
            gate_phase(h1_s, x_s[1][s], zr1);
        } else {
            epi_unit(0, j, cA0, h0_s);
            if (hasB) epi_unit(0, 96 + j, cB0, h0_s);
        }
        __syncthreads();
    }
    // Tail: h(row1, 255).
    if (isEpi) {
        epi_unit(1, j, cA1, h1_s);
        if (hasB) epi_unit(1, 96 + j, cB1, h1_s);
    }
    __syncthreads();

    // Final projection: out[r] = h_final . Wout + bout
    if (t < HID) {
        float w = Wout[t];
        red0[t] = h0_s[t] * w;
        red1[t] = h1_s[t] * w;
    }
    __syncthreads();
    if (t == 0) {
        float s = bout[0];
        for (int k = 0; k < HID; k++) s += red0[k];
        out[r0] = s;
    }
    if (t == 1) {
        float s = bout[0];
        for (int k = 0; k < HID; k++) s += red1[k];
        out[r0 + 1] = s;
    }
}

// ---------------------------------------------------------------------------
// Launch. Input order (metadata.txt): x, W1H, b1H, W1L, b1L, W2H, b2H, W2L,
// b2L, Wih1, Whh1, b1, Wih2, Whh2, b2, Wih3, Whh3, b3, Wout, bout.
// Only the low-pass + LSTM-3 inputs are used.
// ---------------------------------------------------------------------------
extern "C" void kernel_launch(void* const* d_in, const int* in_sizes, int n_in,
                              void* d_out, int out_size)
{
    const float* x    = (const float*)d_in[0];
    const float* W1L  = (const float*)d_in[3];
    const float* b1L  = (const float*)d_in[4];
    const float* W2L  = (const float*)d_in[7];
    const float* b2L  = (const float*)d_in[8];
    const float* Wih3 = (const float*)d_in[15];
    const float* Whh3 = (const float*)d_in[16];
    const float* b3   = (const float*)d_in[17];
    const float* Wout = (const float*)d_in[18];
    const float* bout = (const float*)d_in[19];
    float* out = (float*)d_out;

    dim3 grid1(16, 8);   // N=1024/64, M=256/32 -> 128 CTAs
    dim3 grid2(8, 8);    // N=512/64,  M=256/32 -> 64 CTAs
    gemm1_kernel<<<grid1, 256>>>(x, W1L, b1L);
    gemm2_kernel<<<grid2, 256>>>(W2L, b2L);
    lstm_kernel<<<128, 896>>>(Wih3, Whh3, b3, Wout, bout, out);
}

// round 14
// speedup vs baseline: 1.4536x; 1.4536x over previous
#include <cuda_runtime.h>

// ---------------------------------------------------------------------------
// MWDLSTMGCT: only the low-pass wavelet chain + LSTM-3 affect the output.
//   xl1 = avgpool2(sigmoid(x @ W1L^T + b1L))        (256 x 512)
//   xl2 = avgpool2(sigmoid(xl1 @ W2L^T + b2L))      (256 x 256)
//   h   = LSTM(xl2 as scalar sequence; Wih3,Whh3,b3), final hidden (256 x 100)
//   out = h @ Wout^T + bout                          (256 x 1)
// ---------------------------------------------------------------------------

#define NBATCH 256
#define HID    100
#define GATES  400   // 4*HID
#define TSTEPS 256

__device__ __align__(16) float g_xl1[256 * 512];
__device__ __align__(16) float g_xl2[256 * 256];

__device__ __forceinline__ float sigf(float x) { return 1.f / (1.f + __expf(-x)); }
// tanh(x) = 1 - 2/(exp(2x)+1); exact saturation.
__device__ __forceinline__ float tanh_fast(float x) {
    return 1.f - 2.f / (__expf(2.f * x) + 1.f);
}

// ---------------------------------------------------------------------------
// Fused GEMM (C = A @ W^T), bias, sigmoid, avgpool2 along N.
// Tile 32(M) x 64(N), K-slices of 32, double-buffered smem, 256 threads,
// microtile 4x2. Bank-conflict-free staging:
//   As rows padded to 36 floats (144B, 16B-aligned; quad k-stride 4 -> bank
//   offsets 0/4/8/12, chunk +16 -> 16/20/24/28: all distinct).
//   Bs rows padded to 66 floats (264B, 8B-aligned; bank offsets 0/2/4/6 and
//   8/10/12/14: all distinct).
// Inner kk loop register-rotated: LDS for kk+1 issued before FFMAs of kk.
// A: [256][K], W: [N][K], out: [256][N/2]
// ---------------------------------------------------------------------------
#define APAD 36
#define BPAD 66

template <int K>
__device__ __forceinline__ void gemm_sig_pool_body(
    const float* __restrict__ A, const float* __restrict__ W,
    const float* __restrict__ bias, float* __restrict__ out, int halfN)
{
    __shared__ __align__(16) float As[2][32 * APAD];
    __shared__ __align__(16) float Bs[2][32 * BPAD];

    const int m0 = blockIdx.y * 32;
    const int n0 = blockIdx.x * 64;
    const int tid = threadIdx.x;

    // B loaders: all 256 threads. Row lmB (0..63), k-chunks lkB..+3, lkB+16..+19.
    const int lmB = tid >> 2;            // 0..63
    const int lkB = (tid & 3) * 4;       // 0,4,8,12
    const float* Bg = W + (n0 + lmB) * K + lkB;
    // A loaders: threads 0..127. Row lmA (0..31), same k-chunk pattern.
    const bool hasA = tid < 128;
    const int lmA = (tid & 127) >> 2;    // 0..31
    const int lkA = (tid & 3) * 4;
    const float* Ag = A + (m0 + lmA) * K + lkA;

    const int tx = tid & 31;   // 2 N-cols
    const int ty = tid >> 5;   // 4 M-rows

    float acc[4][2] = {};
    const int NT = K / 32;

    float4 aLo, aHi, bLo, bHi;
    auto ldg = [&](int s) {
        bLo = *(const float4*)(Bg + s * 32);
        bHi = *(const float4*)(Bg + s * 32 + 16);
        if (hasA) {
            aLo = *(const float4*)(Ag + s * 32);
            aHi = *(const float4*)(Ag + s * 32 + 16);
        }
    };
    auto stage = [&](int buf) {
        float* Bd = &Bs[buf][0];
        Bd[(lkB + 0) * BPAD + lmB] = bLo.x;
        Bd[(lkB + 1) * BPAD + lmB] = bLo.y;
        Bd[(lkB + 2) * BPAD + lmB] = bLo.z;
        Bd[(lkB + 3) * BPAD + lmB] = bLo.w;
        Bd[(lkB + 16) * BPAD + lmB] = bHi.x;
        Bd[(lkB + 17) * BPAD + lmB] = bHi.y;
        Bd[(lkB + 18) * BPAD + lmB] = bHi.z;
        Bd[(lkB + 19) * BPAD + lmB] = bHi.w;
        if (hasA) {
            float* Ad = &As[buf][0];
            Ad[(lkA + 0) * APAD + lmA] = aLo.x;
            Ad[(lkA + 1) * APAD + lmA] = aLo.y;
            Ad[(lkA + 2) * APAD + lmA] = aLo.z;
            Ad[(lkA + 3) * APAD + lmA] = aLo.w;
            Ad[(lkA + 16) * APAD + lmA] = aHi.x;
            Ad[(lkA + 17) * APAD + lmA] = aHi.y;
            Ad[(lkA + 18) * APAD + lmA] = aHi.z;
            Ad[(lkA + 19) * APAD + lmA] = aHi.w;
        }
    };
    auto compute = [&](int buf) {
        const float* Ab = &As[buf][ty * 4];
        const float* Bb = &Bs[buf][tx * 2];
        float4 av = *(const float4*)(Ab);
        float2 bv = *(const float2*)(Bb);
        #pragma unroll
        for (int kk = 0; kk < 32; kk++) {
            float4 avn = av; float2 bvn = bv;
            if (kk < 31) {
                avn = *(const float4*)(Ab + (kk + 1) * APAD);
                bvn = *(const float2*)(Bb + (kk + 1) * BPAD);
            }
            acc[0][0] = fmaf(av.x, bv.x, acc[0][0]);
            acc[0][1] = fmaf(av.x, bv.y, acc[0][1]);
            acc[1][0] = fmaf(av.y, bv.x, acc[1][0]);
            acc[1][1] = fmaf(av.y, bv.y, acc[1][1]);
            acc[2][0] = fmaf(av.z, bv.x, acc[2][0]);
            acc[2][1] = fmaf(av.z, bv.y, acc[2][1]);
            acc[3][0] = fmaf(av.w, bv.x, acc[3][0]);
            acc[3][1] = fmaf(av.w, bv.y, acc[3][1]);
            av = avn; bv = bvn;
        }
    };

    ldg(0);
    stage(0);
    __syncthreads();

    for (int tI = 0; tI < NT; tI++) {
        if (tI + 1 < NT) ldg(tI + 1);       // LDG in flight during compute
        compute(tI & 1);
        if (tI + 1 < NT) {
            stage((tI & 1) ^ 1);
            __syncthreads();
        }
    }

    const float bn0 = bias[n0 + tx * 2 + 0];
    const float bn1 = bias[n0 + tx * 2 + 1];
    const int ocol = (n0 >> 1) + tx;
    #pragma unroll
    for (int i = 0; i < 4; i++) {
        const int m = m0 + ty * 4 + i;
        float s0 = sigf(acc[i][0] + bn0);
        float s1 = sigf(acc[i][1] + bn1);
        out[m * halfN + ocol] = 0.5f * (s0 + s1);
    }
}

__global__ void __launch_bounds__(256) gemm1_kernel(
    const float* __restrict__ A, const float* __restrict__ W,
    const float* __restrict__ bias)
{
    gemm_sig_pool_body<1024>(A, W, bias, g_xl1, 512);
}

__global__ void __launch_bounds__(256) gemm2_kernel(
    const float* __restrict__ W, const float* __restrict__ bias)
{
    gemm_sig_pool_body<512>(g_xl1, W, bias, g_xl2, 256);
}

// ---------------------------------------------------------------------------
// LSTM-3 (R10 structure, proven 361us): persistent per-CTA, 2 batch rows per
// CTA, SPLIT-K gate GEMV. 832 threads (26 warps, 78-reg cap):
//   t in [0,400)   : half-A of gate t, k in [0,50), 50 weights in regs,
//                    plus the wih*x + b term.
//   t in [400,800) : half-B of gate t-400, k in [50,100), wih=b=0 so the
//                    instruction sequence is IDENTICAL (no divergence).
// Epilogue: threads 0..199, one (row, hidden-unit) each; z = zA + zB.
// ---------------------------------------------------------------------------
__global__ void __launch_bounds__(832, 1) lstm_kernel(
    const float* __restrict__ Wih, const float* __restrict__ Whh,
    const float* __restrict__ b3,  const float* __restrict__ Wout,
    const float* __restrict__ bout, float* __restrict__ out)
{
    const int r0 = blockIdx.x * 2;
    const int t = threadIdx.x;

    __shared__ __align__(8) float2 h_s[HID];
    __shared__ float zA[2][GATES];
    __shared__ float zB[2][GATES];
    __shared__ float x_s[2][TSTEPS];
    __shared__ float red0[HID], red1[HID];

    const bool isGate = t < 800;
    const bool halfA = t < 400;
    const int g = halfA ? t : t - 400;
    const int kb = halfA ? 0 : 50;

    float wreg[50];
    float wih_g = 0.f, bg = 0.f;
    float* zdst0 = &zA[0][0];
    float* zdst1 = &zA[1][0];
    if (isGate) {
        const float* wrow = Whh + g * HID + kb;
        #pragma unroll
        for (int k = 0; k < 50; k += 2) {
            float2 w = *(const float2*)(wrow + k);
            wreg[k] = w.x; wreg[k + 1] = w.y;
        }
        if (halfA) { wih_g = Wih[g]; bg = b3[g]; }
        zdst0 = halfA ? &zA[0][g] : &zB[0][g];
        zdst1 = halfA ? &zA[1][g] : &zB[1][g];
    }
    if (t < TSTEPS) {
        x_s[0][t] = g_xl2[r0 * TSTEPS + t];
        x_s[1][t] = g_xl2[(r0 + 1) * TSTEPS + t];
    }
    if (t < HID) h_s[t] = make_float2(0.f, 0.f);
    float c_st = 0.f;   // t<100: row0 unit t; 100..199: row1 unit t-100
    __syncthreads();

    for (int step = 0; step < TSTEPS; step++) {
        if (isGate) {
            float z0 = fmaf(wih_g, x_s[0][step], bg);
            float z1 = fmaf(wih_g, x_s[1][step], bg);
            const float2* hp = &h_s[kb];
            #pragma unroll
            for (int k = 0; k < 50; k++) {
                float2 h = hp[k];
                z0 = fmaf(wreg[k], h.x, z0);
                z1 = fmaf(wreg[k], h.y, z1);
            }
            *zdst0 = z0;
            *zdst1 = z1;
        }
        __syncthreads();
        if (t < 2 * HID) {
            const int row = (t >= HID) ? 1 : 0;
            const int j = t - row * HID;
            float iz = zA[row][j]           + zB[row][j];
            float fz = zA[row][HID + j]     + zB[row][HID + j];
            float gz = zA[row][2 * HID + j] + zB[row][2 * HID + j];
            float oz = zA[row][3 * HID + j] + zB[row][3 * HID + j];
            c_st = sigf(fz) * c_st + sigf(iz) * tanh_fast(gz);
            float h = sigf(oz) * tanh_fast(c_st);
            ((float*)&h_s[j])[row] = h;
        }
        __syncthreads();
    }

    // Final projection: out[r] = h_final . Wout + bout
    if (t < HID) {
        float w = Wout[t];
        red0[t] = h_s[t].x * w;
        red1[t] = h_s[t].y * w;
    }
    __syncthreads();
    if (t == 0) {
        float s = bout[0];
        for (int k = 0; k < HID; k++) s += red0[k];
        out[r0] = s;
    }
    if (t == 1) {
        float s = bout[0];
        for (int k = 0; k < HID; k++) s += red1[k];
        out[r0 + 1] = s;
    }
}

// ---------------------------------------------------------------------------
// Launch. Input order (metadata.txt): x, W1H, b1H, W1L, b1L, W2H, b2H, W2L,
// b2L, Wih1, Whh1, b1, Wih2, Whh2, b2, Wih3, Whh3, b3, Wout, bout.
// Only the low-pass + LSTM-3 inputs are used.
// ---------------------------------------------------------------------------
extern "C" void kernel_launch(void* const* d_in, const int* in_sizes, int n_in,
                              void* d_out, int out_size)
{
    const float* x    = (const float*)d_in[0];
    const float* W1L  = (const float*)d_in[3];
    const float* b1L  = (const float*)d_in[4];
    const float* W2L  = (const float*)d_in[7];
    const float* b2L  = (const float*)d_in[8];
    const float* Wih3 = (const float*)d_in[15];
    const float* Whh3 = (const float*)d_in[16];
    const float* b3   = (const float*)d_in[17];
    const float* Wout = (const float*)d_in[18];
    const float* bout = (const float*)d_in[19];
    float* out = (float*)d_out;

    dim3 grid1(16, 8);   // N=1024/64, M=256/32 -> 128 CTAs
    dim3 grid2(8, 8);    // N=512/64,  M=256/32 -> 64 CTAs
    gemm1_kernel<<<grid1, 256>>>(x, W1L, b1L);
    gemm2_kernel<<<grid2, 256>>>(W2L, b2L);
    lstm_kernel<<<128, 832>>>(Wih3, Whh3, b3, Wout, bout, out);
}

// round 15
// speedup vs baseline: 1.5587x; 1.0723x over previous
#include <cuda_runtime.h>

// ---------------------------------------------------------------------------
// MWDLSTMGCT: only the low-pass wavelet chain + LSTM-3 affect the output.
//   xl1 = avgpool2(sigmoid(x @ W1L^T + b1L))        (256 x 512)
//   xl2 = avgpool2(sigmoid(xl1 @ W2L^T + b2L))      (256 x 256)
//   h   = LSTM(xl2 as scalar sequence; Wih3,Whh3,b3), final hidden (256 x 100)
//   out = h @ Wout^T + bout                          (256 x 1)
// ---------------------------------------------------------------------------

#define NBATCH 256
#define HID    100
#define GATES  400   // 4*HID
#define TSTEPS 256
#define ZSTR   104   // z-array stride per gate type (bank-conflict-free quad reads)

__device__ __align__(16) float g_xl1[256 * 512];
__device__ __align__(16) float g_xl2[256 * 256];

__device__ __forceinline__ float sigf(float x) { return 1.f / (1.f + __expf(-x)); }
// tanh(x) = 1 - 2/(exp(2x)+1); exact saturation.
__device__ __forceinline__ float tanh_fast(float x) {
    return 1.f - 2.f / (__expf(2.f * x) + 1.f);
}

// ---------------------------------------------------------------------------
// Fused GEMM (C = A @ W^T), bias, sigmoid, avgpool2 along N.  (R14, proven)
// Tile 32(M) x 64(N), K-slices of 32, double-buffered smem, 256 threads,
// microtile 4x2, conflict-free padded staging, register-rotated kk loop.
// ---------------------------------------------------------------------------
#define APAD 36
#define BPAD 66

template <int K>
__device__ __forceinline__ void gemm_sig_pool_body(
    const float* __restrict__ A, const float* __restrict__ W,
    const float* __restrict__ bias, float* __restrict__ out, int halfN)
{
    __shared__ __align__(16) float As[2][32 * APAD];
    __shared__ __align__(16) float Bs[2][32 * BPAD];

    const int m0 = blockIdx.y * 32;
    const int n0 = blockIdx.x * 64;
    const int tid = threadIdx.x;

    const int lmB = tid >> 2;
    const int lkB = (tid & 3) * 4;
    const float* Bg = W + (n0 + lmB) * K + lkB;
    const bool hasA = tid < 128;
    const int lmA = (tid & 127) >> 2;
    const int lkA = (tid & 3) * 4;
    const float* Ag = A + (m0 + lmA) * K + lkA;

    const int tx = tid & 31;
    const int ty = tid >> 5;

    float acc[4][2] = {};
    const int NT = K / 32;

    float4 aLo, aHi, bLo, bHi;
    auto ldg = [&](int s) {
        bLo = *(const float4*)(Bg + s * 32);
        bHi = *(const float4*)(Bg + s * 32 + 16);
        if (hasA) {
            aLo = *(const float4*)(Ag + s * 32);
            aHi = *(const float4*)(Ag + s * 32 + 16);
        }
    };
    auto stage = [&](int buf) {
        float* Bd = &Bs[buf][0];
        Bd[(lkB + 0) * BPAD + lmB] = bLo.x;
        Bd[(lkB + 1) * BPAD + lmB] = bLo.y;
        Bd[(lkB + 2) * BPAD + lmB] = bLo.z;
        Bd[(lkB + 3) * BPAD + lmB] = bLo.w;
        Bd[(lkB + 16) * BPAD + lmB] = bHi.x;
        Bd[(lkB + 17) * BPAD + lmB] = bHi.y;
        Bd[(lkB + 18) * BPAD + lmB] = bHi.z;
        Bd[(lkB + 19) * BPAD + lmB] = bHi.w;
        if (hasA) {
            float* Ad = &As[buf][0];
            Ad[(lkA + 0) * APAD + lmA] = aLo.x;
            Ad[(lkA + 1) * APAD + lmA] = aLo.y;
            Ad[(lkA + 2) * APAD + lmA] = aLo.z;
            Ad[(lkA + 3) * APAD + lmA] = aLo.w;
            Ad[(lkA + 16) * APAD + lmA] = aHi.x;
            Ad[(lkA + 17) * APAD + lmA] = aHi.y;
            Ad[(lkA + 18) * APAD + lmA] = aHi.z;
            Ad[(lkA + 19) * APAD + lmA] = aHi.w;
        }
    };
    auto compute = [&](int buf) {
        const float* Ab = &As[buf][ty * 4];
        const float* Bb = &Bs[buf][tx * 2];
        float4 av = *(const float4*)(Ab);
        float2 bv = *(const float2*)(Bb);
        #pragma unroll
        for (int kk = 0; kk < 32; kk++) {
            float4 avn = av; float2 bvn = bv;
            if (kk < 31) {
                avn = *(const float4*)(Ab + (kk + 1) * APAD);
                bvn = *(const float2*)(Bb + (kk + 1) * BPAD);
            }
            acc[0][0] = fmaf(av.x, bv.x, acc[0][0]);
            acc[0][1] = fmaf(av.x, bv.y, acc[0][1]);
            acc[1][0] = fmaf(av.y, bv.x, acc[1][0]);
            acc[1][1] = fmaf(av.y, bv.y, acc[1][1]);
            acc[2][0] = fmaf(av.z, bv.x, acc[2][0]);
            acc[2][1] = fmaf(av.z, bv.y, acc[2][1]);
            acc[3][0] = fmaf(av.w, bv.x, acc[3][0]);
            acc[3][1] = fmaf(av.w, bv.y, acc[3][1]);
            av = avn; bv = bvn;
        }
    };

    ldg(0);
    stage(0);
    __syncthreads();

    for (int tI = 0; tI < NT; tI++) {
        if (tI + 1 < NT) ldg(tI + 1);
        compute(tI & 1);
        if (tI + 1 < NT) {
            stage((tI & 1) ^ 1);
            __syncthreads();
        }
    }

    const float bn0 = bias[n0 + tx * 2 + 0];
    const float bn1 = bias[n0 + tx * 2 + 1];
    const int ocol = (n0 >> 1) + tx;
    #pragma unroll
    for (int i = 0; i < 4; i++) {
        const int m = m0 + ty * 4 + i;
        float s0 = sigf(acc[i][0] + bn0);
        float s1 = sigf(acc[i][1] + bn1);
        out[m * halfN + ocol] = 0.5f * (s0 + s1);
    }
}

__global__ void __launch_bounds__(256) gemm1_kernel(
    const float* __restrict__ A, const float* __restrict__ W,
    const float* __restrict__ bias)
{
    gemm_sig_pool_body<1024>(A, W, bias, g_xl1, 512);
}

__global__ void __launch_bounds__(256) gemm2_kernel(
    const float* __restrict__ W, const float* __restrict__ bias)
{
    gemm_sig_pool_body<512>(g_xl1, W, bias, g_xl2, 256);
}

// ---------------------------------------------------------------------------
// LSTM-3: persistent per-CTA, 2 batch rows per CTA, SPLIT-K gate GEMV +
// QUAD-PARALLEL epilogue. 800 threads (25 warps, 81-reg cap):
// Gate phase (unchanged, proven):
//   t in [0,400)   : half-A of gate t, k in [0,50), 50 weights in regs,
//                    plus the wih*x + b term.
//   t in [400,800) : half-B of gate t-400, k in [50,100), wih=b=0 (identical
//                    instruction stream, no divergence).
//   z stored with stride ZSTR=104 per gate type (conflict-free quad reads).
// Epilogue: ALL 800 threads. q=t&3 -> gate type, u=t>>2 -> (row,unit).
//   Each lane computes ONE transcendental (4 in parallel per unit), lane q=0
//   gathers i,f,g,o via 3 shfl_xor, updates c, computes h, stores it.
//   Nonlinearity unified branch-free: tanh(x) = 2*sigmoid(2x)-1.
// ---------------------------------------------------------------------------
__global__ void __launch_bounds__(800, 1) lstm_kernel(
    const float* __restrict__ Wih, const float* __restrict__ Whh,
    const float* __restrict__ b3,  const float* __restrict__ Wout,
    const float* __restrict__ bout, float* __restrict__ out)
{
    const int r0 = blockIdx.x * 2;
    const int t = threadIdx.x;

    __shared__ __align__(8) float2 h_s[HID];
    __shared__ float zA[2][4 * ZSTR];
    __shared__ float zB[2][4 * ZSTR];
    __shared__ float x_s[2][TSTEPS];
    __shared__ float red0[HID], red1[HID];

    const bool halfA = t < 400;
    const int g = halfA ? t : t - 400;
    const int kb = halfA ? 0 : 50;
    const int zoff = (g / 100) * ZSTR + (g % 100);   // strided z slot for gate g

    float wreg[50];
    float wih_g = 0.f, bg = 0.f;
    {
        const float* wrow = Whh + g * HID + kb;
        #pragma unroll
        for (int k = 0; k < 50; k += 2) {
            float2 w = *(const float2*)(wrow + k);
            wreg[k] = w.x; wreg[k + 1] = w.y;
        }
        if (halfA) { wih_g = Wih[g]; bg = b3[g]; }
    }
    float* zdst0 = halfA ? &zA[0][zoff] : &zB[0][zoff];
    float* zdst1 = halfA ? &zA[1][zoff] : &zB[1][zoff];

    if (t < TSTEPS) {
        x_s[0][t] = g_xl2[r0 * TSTEPS + t];
        x_s[1][t] = g_xl2[(r0 + 1) * TSTEPS + t];
    }
    if (t < HID) h_s[t] = make_float2(0.f, 0.f);

    // Epilogue mapping: q = gate type, u = (row, unit).
    const int q = t & 3;
    const int uu = t >> 2;                 // 0..199
    const int erow = (uu >= HID) ? 1 : 0;
    const int ej = uu - erow * HID;        // 0..99
    const int zread = q * ZSTR + ej;
    const bool isG = (q == 2);             // candidate-gate lane -> tanh
    float c_st = 0.f;                      // lane q==0 holds c for unit (erow, ej)
    __syncthreads();

    for (int step = 0; step < TSTEPS; step++) {
        // ---- gate phase: z(row0), z(row1) for this thread's half-gate ----
        {
            float z0 = fmaf(wih_g, x_s[0][step], bg);
            float z1 = fmaf(wih_g, x_s[1][step], bg);
            const float2* hp = &h_s[kb];
            #pragma unroll
            for (int k = 0; k < 50; k++) {
                float2 h = hp[k];
                z0 = fmaf(wreg[k], h.x, z0);
                z1 = fmaf(wreg[k], h.y, z1);
            }
            *zdst0 = z0;
            *zdst1 = z1;
        }
        __syncthreads();
        // ---- epilogue: quad-parallel transcendentals + shuffle combine ----
        {
            float zq = zA[erow][zread] + zB[erow][zread];
            float xin = isG ? 2.f * zq : zq;
            float s = sigf(xin);
            float v = isG ? 2.f * s - 1.f : s;      // q: 0->sig(i) 1->sig(f) 2->tanh(g) 3->sig(o)
            float w  = __shfl_xor_sync(0xFFFFFFFFu, v, 1);  // q0 gets f, q2 gets o
            float u2 = __shfl_xor_sync(0xFFFFFFFFu, v, 2);  // q0 gets tanh(g)
            float u3 = __shfl_xor_sync(0xFFFFFFFFu, w, 2);  // q0 gets sig(o)
            if (q == 0) {
                c_st = w * c_st + v * u2;
                float h = u3 * tanh_fast(c_st);
                ((float*)&h_s[ej])[erow] = h;
            }
        }
        __syncthreads();
    }

    // Final projection: out[r] = h_final . Wout + bout
    if (t < HID) {
        float w = Wout[t];
        red0[t] = h_s[t].x * w;
        red1[t] = h_s[t].y * w;
    }
    __syncthreads();
    if (t == 0) {
        float s = bout[0];
        for (int k = 0; k < HID; k++) s += red0[k];
        out[r0] = s;
    }
    if (t == 1) {
        float s = bout[0];
        for (int k = 0; k < HID; k++) s += red1[k];
        out[r0 + 1] = s;
    }
}

// ---------------------------------------------------------------------------
// Launch. Input order (metadata.txt): x, W1H, b1H, W1L, b1L, W2H, b2H, W2L,
// b2L, Wih1, Whh1, b1, Wih2, Whh2, b2, Wih3, Whh3, b3, Wout, bout.
// Only the low-pass + LSTM-3 inputs are used.
// ---------------------------------------------------------------------------
extern "C" void kernel_launch(void* const* d_in, const int* in_sizes, int n_in,
                              void* d_out, int out_size)
{
    const float* x    = (const float*)d_in[0];
    const float* W1L  = (const float*)d_in[3];
    const float* b1L  = (const float*)d_in[4];
    const float* W2L  = (const float*)d_in[7];
    const float* b2L  = (const float*)d_in[8];
    const float* Wih3 = (const float*)d_in[15];
    const float* Whh3 = (const float*)d_in[16];
    const float* b3   = (const float*)d_in[17];
    const float* Wout = (const float*)d_in[18];
    const float* bout = (const float*)d_in[19];
    float* out = (float*)d_out;

    dim3 grid1(16, 8);   // N=1024/64, M=256/32 -> 128 CTAs
    dim3 grid2(8, 8);    // N=512/64,  M=256/32 -> 64 CTAs
    gemm1_kernel<<<grid1, 256>>>(x, W1L, b1L);
    gemm2_kernel<<<grid2, 256>>>(W2L, b2L);
    lstm_kernel<<<128, 800>>>(Wih3, Whh3, b3, Wout, bout, out);
}